// round 13
// baseline (speedup 1.0000x reference)
#include <cuda_runtime.h>
#include <cuda_fp16.h>
#include <math.h>
#include <cstdint>

#define H 768
#define SEQ 2048
#define BATCH 4
#define NTOK (BATCH * SEQ)   // 8192
#define L 9
#define M_WIN 5
#define W_WIN (2 * M_WIN + 1)  // 11
#define K2H (2 * H)            // 1536
#define TOK12 16               // tokens per k12 block
#define NW12 (TOK12 + 2 * M_WIN)  // 26 halo scores

// ---------------- scratch (__device__ globals; no allocs allowed) ----------
__device__ float g_base[NTOK * L];
__device__ float g_h[NTOK * H];          // 25 MB
__device__ __half g_A[NTOK * K2H];       // 25 MB, fp16 [x|ctx]
__device__ __half g_B[H * K2H];          // W1^T fp16 [N=768][K=1536]

// ---------------- PTX helpers ----------------------------------------------
__device__ __forceinline__ uint32_t smem_u32(const void* p) {
    uint32_t a;
    asm("{ .reg .u64 t; cvta.to.shared.u64 t, %1; cvt.u32.u64 %0, t; }" : "=r"(a) : "l"(p));
    return a;
}
__device__ __forceinline__ void cp16(uint32_t dst, const void* src) {
    asm volatile("cp.async.cg.shared.global [%0], [%1], 16;" :: "r"(dst), "l"(src));
}
__device__ __forceinline__ void cp_commit() {
    asm volatile("cp.async.commit_group;" ::: "memory");
}
template <int N>
__device__ __forceinline__ void cp_wait() {
    asm volatile("cp.async.wait_group %0;" :: "n"(N) : "memory");
}
__device__ __forceinline__ void ldsm_x4(uint32_t* r, uint32_t addr) {
    asm volatile("ldmatrix.sync.aligned.m8n8.x4.shared.b16 {%0,%1,%2,%3}, [%4];"
                 : "=r"(r[0]), "=r"(r[1]), "=r"(r[2]), "=r"(r[3]) : "r"(addr));
}
__device__ __forceinline__ void mma_f16(float* c, const uint32_t* a, const uint32_t* b) {
    asm volatile("mma.sync.aligned.m16n8k16.row.col.f32.f16.f16.f32 "
                 "{%0,%1,%2,%3}, {%4,%5,%6,%7}, {%8,%9}, {%0,%1,%2,%3};"
                 : "+f"(c[0]), "+f"(c[1]), "+f"(c[2]), "+f"(c[3])
                 : "r"(a[0]), "r"(a[1]), "r"(a[2]), "r"(a[3]), "r"(b[0]), "r"(b[1]));
}

// ============================================================
// prep: W1 [K2H][H] fp32 -> W1^T fp16 [H][K2H]
// ============================================================
__global__ __launch_bounds__(256) void kprep_w(const float* __restrict__ W1)
{
    __shared__ float tile[32][33];
    int tx = threadIdx.x, ty = threadIdx.y;           // block (32,8)
    int n = blockIdx.x * 32 + tx;                     // H dim
    int k = blockIdx.y * 32 + ty;                     // K2H dim
#pragma unroll
    for (int j = 0; j < 32; j += 8)
        tile[ty + j][tx] = W1[(size_t)(k + j) * H + n];
    __syncthreads();
    int ko = blockIdx.y * 32 + tx;
    int no = blockIdx.x * 32 + ty;
#pragma unroll
    for (int j = 0; j < 32; j += 8)
        g_B[(size_t)(no + j) * K2H + ko] = __float2half(tile[tx][ty + j]);
}

// ============================================================
// K12: fused scores + base logits + window softmax + context
//      16 tokens per block, 256 threads
// ============================================================
__global__ __launch_bounds__(256) void k12_fused(
    const float* __restrict__ x, const float* __restrict__ wa,
    const float* __restrict__ Wc, const float* __restrict__ bc)
{
    const int row0 = blockIdx.x * TOK12;
    const int b = row0 / SEQ;
    const int s0 = row0 % SEQ;
    const int tid = threadIdx.x;
    const int lane = tid & 31, warp = tid >> 5;
    const float* bbase = x + (size_t)b * SEQ * H;

    __shared__ float scbuf[NW12];
    __shared__ float attn[TOK12][W_WIN + 1];

    // ---- phase 1a: 26 halo scores (ba omitted: softmax shift-invariant) ----
    for (int j = warp; j < NW12; j += 8) {
        int sseq = s0 - M_WIN + j;
        int sc = min(max(sseq, 0), SEQ - 1);
        const float* xr = bbase + (size_t)sc * H;
        float d = 0.f;
#pragma unroll
        for (int k = 0; k < 12; k++) {
            int h2 = 2 * lane + 64 * k;
            float2 v = *(const float2*)&xr[h2];
            float2 w2 = *(const float2*)&wa[h2];
            d += v.x * w2.x + v.y * w2.y;
        }
#pragma unroll
        for (int o = 16; o > 0; o >>= 1) d += __shfl_down_sync(0xffffffffu, d, o);
        if (lane == 0) scbuf[j] = d;
    }

    // ---- phase 1b: base logits for own 2 tokens per warp ----
#pragma unroll
    for (int tt = 0; tt < 2; tt++) {
        const int t = warp * 2 + tt;
        const float* xr = bbase + (size_t)(s0 + t) * H;
        float acc[L];
#pragma unroll
        for (int l = 0; l < L; l++) acc[l] = 0.f;
#pragma unroll
        for (int k = 0; k < 12; k++) {
            int h2 = 2 * lane + 64 * k;
            float2 v = *(const float2*)&xr[h2];
            const float* w0 = &Wc[(size_t)h2 * L];
#pragma unroll
            for (int l = 0; l < L; l++) acc[l] += v.x * w0[l] + v.y * w0[l + L];
        }
#pragma unroll
        for (int l = 0; l < L; l++) {
#pragma unroll
            for (int o = 16; o > 0; o >>= 1)
                acc[l] += __shfl_down_sync(0xffffffffu, acc[l], o);
        }
        if (lane == 0) {
#pragma unroll
            for (int l = 0; l < L; l++)
                g_base[(row0 + t) * L + l] = acc[l] + bc[l];
        }
    }
    __syncthreads();

    // ---- phase 2: per-token softmax (one lane per token) ----
    if (tid < TOK12) {
        const int i = tid;
        const int sseq = s0 + i;
        float e[W_WIN];
        float m = -INFINITY;
#pragma unroll
        for (int w = 0; w < W_WIN; w++) {
            int idx = sseq - M_WIN + w;
            bool v = (idx >= 0) && (idx < SEQ);
            float scv = v ? scbuf[i + w] : -INFINITY;
            e[w] = scv;
            m = fmaxf(m, scv);
        }
        float sum = 0.f;
#pragma unroll
        for (int w = 0; w < W_WIN; w++) {
            int idx = sseq - M_WIN + w;
            bool v = (idx >= 0) && (idx < SEQ);
            float ev = v ? expf(e[w] - m) : 0.f;
            e[w] = ev;
            sum += ev;
        }
        float inv = 1.f / sum;
#pragma unroll
        for (int w = 0; w < W_WIN; w++) attn[i][w] = e[w] * inv;
    }
    __syncthreads();

    // ---- phase 3: weighted context + emit [x|ctx] fp16 ----
#pragma unroll
    for (int tt = 0; tt < 2; tt++) {
        const int t = warp * 2 + tt;
        const int sseq = s0 + t;
        const float* rp[W_WIN];
        float aw[W_WIN];
#pragma unroll
        for (int w = 0; w < W_WIN; w++) {
            int idx = min(max(sseq - M_WIN + w, 0), SEQ - 1);
            rp[w] = bbase + (size_t)idx * H;
            aw[w] = attn[t][w];
        }
        __half* arow = g_A + (size_t)(row0 + t) * K2H;
#pragma unroll
        for (int k = 0; k < 12; k++) {
            int h2 = 2 * lane + 64 * k;
            float2 xc = *(const float2*)&rp[M_WIN][h2];
            float ax = 0.f, ay = 0.f;
#pragma unroll
            for (int w = 0; w < W_WIN; w++) {
                float2 v = *(const float2*)&rp[w][h2];
                ax += aw[w] * v.x;
                ay += aw[w] * v.y;
            }
            *(__half2*)&arow[h2] = __floats2half2_rn(xc.x, xc.y);
            *(__half2*)&arow[H + h2] = __floats2half2_rn(ax, ay);
        }
    }
}

// ============================================================
// K3: single-pass fp16 HMMA GEMM: g_h = [x|ctx] @ W1 + b1
// BM=128 BN=128 BK=64(halfs = 128B rows), 3-stage cp.async
// single-sync pipeline, 256 thr (8 warps: 4M x 2N, tile 32x64),
// 2 CTAs/SM (97 KB smem each)
// ============================================================
#define BM3 128
#define BN3 128
#define BK3 64
#define NIT (K2H / BK3)            // 24
#define NSTG 3
#define SA 0
#define SB (16 * 1024)
#define STAGE_BYTES (32 * 1024)
#define SMEM_TOTAL3 (1024 + NSTG * STAGE_BYTES)

__global__ __launch_bounds__(256, 2) void k3_mma(const float* __restrict__ b1)
{
    extern __shared__ char smem_raw[];
    uint32_t sraw = smem_u32(smem_raw);
    const uint32_t sbase = (sraw + 1023u) & ~1023u;

    const int tid = threadIdx.x;
    const int lane = tid & 31, wid = tid >> 5;
    const int warpM = wid & 3;        // 4 M warps
    const int warpN = wid >> 2;       // 2 N warps
    const int m0 = blockIdx.y * BM3;
    const int n0 = blockIdx.x * BN3;

    // ---- gmem load roles: thread t -> row t>>1, chunks (t&1)*4 .. +3 ----
    const int ldRow = tid >> 1;
    const int ldC0 = (tid & 1) * 4;
    const __half* gA = g_A + (size_t)(m0 + ldRow) * K2H + ldC0 * 8;
    const __half* gB = g_B + (size_t)(n0 + ldRow) * K2H + ldC0 * 8;
    uint32_t dOff[4];
#pragma unroll
    for (int i = 0; i < 4; i++) {
        int c = ldC0 + i;
        dOff[i] = ldRow * 128 + ((c ^ (ldRow & 7)) << 4);
    }

    // ---- ldmatrix address prep ----
    int aRow[2], aX[2];
    aRow[0] = warpM * 32 + (lane & 15);
    aRow[1] = aRow[0] + 16;
    aX[0] = aRow[0] & 7;
    aX[1] = aRow[1] & 7;
    const int aCB = lane >> 4;
    int bRow[4], bX[4];
#pragma unroll
    for (int p = 0; p < 4; p++) {
        bRow[p] = warpN * 64 + p * 16 + (lane & 7) + ((lane >> 4) << 3);
        bX[p] = bRow[p] & 7;
    }
    const int bCB = (lane >> 3) & 1;

    float c[2][8][4];
#pragma unroll
    for (int f = 0; f < 2; f++)
#pragma unroll
        for (int j = 0; j < 8; j++)
#pragma unroll
            for (int q = 0; q < 4; q++) c[f][j][q] = 0.f;

    // ---- prologue: stages 0..NSTG-2 ----
#pragma unroll
    for (int st = 0; st < NSTG - 1; st++) {
        uint32_t sd = sbase + st * STAGE_BYTES;
        const int kb = st * BK3;
#pragma unroll
        for (int i = 0; i < 4; i++) {
            cp16(sd + SA + dOff[i], gA + kb + i * 8);
            cp16(sd + SB + dOff[i], gB + kb + i * 8);
        }
        cp_commit();
    }

    for (int it = 0; it < NIT; ++it) {
        cp_wait<NSTG - 2>();      // stage `it` resident
        __syncthreads();          // all warps done reading stage it-1

        const int pf = it + NSTG - 1;
        if (pf < NIT) {
            const uint32_t sn = sbase + (pf % NSTG) * STAGE_BYTES;
            const int kb = pf * BK3;
#pragma unroll
            for (int i = 0; i < 4; i++) {
                cp16(sn + SA + dOff[i], gA + kb + i * 8);
                cp16(sn + SB + dOff[i], gB + kb + i * 8);
            }
        }
        cp_commit();

        const uint32_t sd = sbase + (it % NSTG) * STAGE_BYTES;
#pragma unroll
        for (int s = 0; s < 4; s++) {          // 4 k16-steps per BK=64
            uint32_t af[2][4], bf[4][4];
#pragma unroll
            for (int f = 0; f < 2; f++) {
                uint32_t off = aRow[f] * 128 + (((2 * s + aCB) ^ aX[f]) << 4);
                ldsm_x4(af[f], sd + SA + off);
            }
#pragma unroll
            for (int p = 0; p < 4; p++) {
                uint32_t off = bRow[p] * 128 + (((2 * s + bCB) ^ bX[p]) << 4);
                ldsm_x4(bf[p], sd + SB + off);
            }
#pragma unroll
            for (int p = 0; p < 4; p++)
#pragma unroll
                for (int f = 0; f < 2; f++) {
                    mma_f16(c[f][2 * p],     af[f], bf[p]);
                    mma_f16(c[f][2 * p + 1], af[f], bf[p] + 2);
                }
        }
    }

    // ---- epilogue: +b1 -> g_h ----
    const int mBase = m0 + warpM * 32 + (lane >> 2);
    const int nBase = n0 + warpN * 64 + (lane & 3) * 2;
#pragma unroll
    for (int f = 0; f < 2; f++) {
#pragma unroll
        for (int j = 0; j < 8; j++) {
            int n = nBase + j * 8;
            float b0 = b1[n], b1v = b1[n + 1];
            int m = mBase + f * 16;
            float2 o0 = make_float2(c[f][j][0] + b0, c[f][j][1] + b1v);
            float2 o1 = make_float2(c[f][j][2] + b0, c[f][j][3] + b1v);
            *(float2*)&g_h[(size_t)m * H + n] = o0;
            *(float2*)&g_h[(size_t)(m + 8) * H + n] = o1;
        }
    }
}

// ============================================================
// K4: layernorm + exact gelu + W2 + combine
// warp-per-row, no block barriers in main loop.
// 256 thr = 8 warps; each warp does 4 rows; 32 rows/block
// ============================================================
#define K4_ROWS 32
__global__ __launch_bounds__(256) void k4_ln_gelu_out(
    const float* __restrict__ gamma, const float* __restrict__ beta,
    const float* __restrict__ W2, const float* __restrict__ b2,
    float* __restrict__ out)
{
    const int tid = threadIdx.x;
    const int lane = tid & 31, wid = tid >> 5;

    __shared__ float w2s[H * L];      // 27 KB
    __shared__ float gb[2 * H];       // 6 KB
    for (int i = tid; i < H * L; i += 256) w2s[i] = W2[i];
    for (int i = tid; i < H; i += 256) { gb[i] = gamma[i]; gb[H + i] = beta[i]; }
    __syncthreads();

#pragma unroll
    for (int r = 0; r < 4; r++) {
        const int row = blockIdx.x * K4_ROWS + wid * 4 + r;
        const float4* hp = (const float4*)(g_h + (size_t)row * H);

        float4 hv[6];
        float s1 = 0.f, s2 = 0.f;
#pragma unroll
        for (int k = 0; k < 6; k++) {
            hv[k] = hp[lane + 32 * k];
            s1 += hv[k].x + hv[k].y + hv[k].z + hv[k].w;
            s2 += hv[k].x * hv[k].x + hv[k].y * hv[k].y
                + hv[k].z * hv[k].z + hv[k].w * hv[k].w;
        }
#pragma unroll
        for (int o = 16; o > 0; o >>= 1) {
            s1 += __shfl_xor_sync(0xffffffffu, s1, o);
            s2 += __shfl_xor_sync(0xffffffffu, s2, o);
        }
        const float mu = s1 * (1.0f / H);
        const float rstd = rsqrtf(s2 * (1.0f / H) - mu * mu + 1e-5f);

        float bl[L];
#pragma unroll
        for (int l = 0; l < L; l++) bl[l] = 0.f;
#pragma unroll
        for (int k = 0; k < 6; k++) {
            const int j = lane + 32 * k;
            float he[4] = {hv[k].x, hv[k].y, hv[k].z, hv[k].w};
#pragma unroll
            for (int e = 0; e < 4; e++) {
                int idx = 4 * j + e;
                float xv = (he[e] - mu) * rstd * gb[idx] + gb[H + idx];
                float g = xv * normcdff(xv);
                const float* w2r = &w2s[idx * L];
#pragma unroll
                for (int l = 0; l < L; l++) bl[l] += g * w2r[l];
            }
        }
#pragma unroll
        for (int l = 0; l < L; l++) {
#pragma unroll
            for (int o = 16; o > 0; o >>= 1)
                bl[l] += __shfl_down_sync(0xffffffffu, bl[l], o);
        }
        if (lane == 0) {
#pragma unroll
            for (int l = 0; l < L; l++)
                out[row * L + l] = 0.5f * g_base[row * L + l] + 0.5f * (bl[l] + b2[l]);
        }
    }
}

// ============================================================
extern "C" void kernel_launch(void* const* d_in, const int* in_sizes, int n_in,
                              void* d_out, int out_size)
{
    const float* x     = (const float*)d_in[0];
    const float* Wc    = (const float*)d_in[1];
    const float* bc    = (const float*)d_in[2];
    const float* wa    = (const float*)d_in[3];
    const float* W1    = (const float*)d_in[5];
    const float* b1    = (const float*)d_in[6];
    const float* gamma = (const float*)d_in[7];
    const float* beta  = (const float*)d_in[8];
    const float* W2    = (const float*)d_in[9];
    const float* b2    = (const float*)d_in[10];
    float* out = (float*)d_out;

    cudaFuncSetAttribute(k3_mma, cudaFuncAttributeMaxDynamicSharedMemorySize, SMEM_TOTAL3);

    kprep_w<<<dim3(H / 32, K2H / 32), dim3(32, 8)>>>(W1);
    k12_fused<<<NTOK / TOK12, 256>>>(x, wa, Wc, bc);
    k3_mma<<<dim3(H / BN3, NTOK / BM3), 256, SMEM_TOTAL3>>>(b1);
    k4_ln_gelu_out<<<NTOK / K4_ROWS, 256>>>(gamma, beta, W2, b2, out);
}

// round 14
// speedup vs baseline: 1.2166x; 1.2166x over previous
#include <cuda_runtime.h>
#include <cuda_fp16.h>
#include <math.h>
#include <cstdint>

#define H 768
#define SEQ 2048
#define BATCH 4
#define NTOK (BATCH * SEQ)   // 8192
#define L 9
#define M_WIN 5
#define W_WIN (2 * M_WIN + 1)  // 11
#define K2H (2 * H)            // 1536
#define TOK12 16               // tokens per k12 block
#define NW12 (TOK12 + 2 * M_WIN)  // 26 halo scores

// ---------------- scratch (__device__ globals; no allocs allowed) ----------
__device__ float g_base[NTOK * L];
__device__ float g_h[NTOK * H];          // 25 MB
__device__ __half g_A[NTOK * K2H];       // 25 MB, fp16 [x|ctx]
__device__ __half g_B[H * K2H];          // W1^T fp16 [N=768][K=1536]

// ---------------- PTX helpers ----------------------------------------------
__device__ __forceinline__ uint32_t smem_u32(const void* p) {
    uint32_t a;
    asm("{ .reg .u64 t; cvta.to.shared.u64 t, %1; cvt.u32.u64 %0, t; }" : "=r"(a) : "l"(p));
    return a;
}
__device__ __forceinline__ void cp16(uint32_t dst, const void* src) {
    asm volatile("cp.async.cg.shared.global [%0], [%1], 16;" :: "r"(dst), "l"(src));
}
__device__ __forceinline__ void cp_commit() {
    asm volatile("cp.async.commit_group;" ::: "memory");
}
template <int N>
__device__ __forceinline__ void cp_wait() {
    asm volatile("cp.async.wait_group %0;" :: "n"(N) : "memory");
}
__device__ __forceinline__ void ldsm_x4(uint32_t* r, uint32_t addr) {
    asm volatile("ldmatrix.sync.aligned.m8n8.x4.shared.b16 {%0,%1,%2,%3}, [%4];"
                 : "=r"(r[0]), "=r"(r[1]), "=r"(r[2]), "=r"(r[3]) : "r"(addr));
}
__device__ __forceinline__ void mma_f16(float* c, const uint32_t* a, const uint32_t* b) {
    asm volatile("mma.sync.aligned.m16n8k16.row.col.f32.f16.f16.f32 "
                 "{%0,%1,%2,%3}, {%4,%5,%6,%7}, {%8,%9}, {%0,%1,%2,%3};"
                 : "+f"(c[0]), "+f"(c[1]), "+f"(c[2]), "+f"(c[3])
                 : "r"(a[0]), "r"(a[1]), "r"(a[2]), "r"(a[3]), "r"(b[0]), "r"(b[1]));
}

// ============================================================
// prep: W1 [K2H][H] fp32 -> W1^T fp16 [H][K2H]
// ============================================================
__global__ __launch_bounds__(256) void kprep_w(const float* __restrict__ W1)
{
    __shared__ float tile[32][33];
    int tx = threadIdx.x, ty = threadIdx.y;           // block (32,8)
    int n = blockIdx.x * 32 + tx;                     // H dim
    int k = blockIdx.y * 32 + ty;                     // K2H dim
#pragma unroll
    for (int j = 0; j < 32; j += 8)
        tile[ty + j][tx] = W1[(size_t)(k + j) * H + n];
    __syncthreads();
    int ko = blockIdx.y * 32 + tx;
    int no = blockIdx.x * 32 + ty;
#pragma unroll
    for (int j = 0; j < 32; j += 8)
        g_B[(size_t)(no + j) * K2H + ko] = __float2half(tile[tx][ty + j]);
}

// ============================================================
// K12: fused scores + base logits + window softmax + context
//      16 tokens per block, 256 threads
// ============================================================
__global__ __launch_bounds__(256) void k12_fused(
    const float* __restrict__ x, const float* __restrict__ wa,
    const float* __restrict__ Wc, const float* __restrict__ bc)
{
    const int row0 = blockIdx.x * TOK12;
    const int b = row0 / SEQ;
    const int s0 = row0 % SEQ;
    const int tid = threadIdx.x;
    const int lane = tid & 31, warp = tid >> 5;
    const float* bbase = x + (size_t)b * SEQ * H;

    __shared__ float scbuf[NW12];
    __shared__ float attn[TOK12][W_WIN + 1];

    // ---- phase 1a: 26 halo scores (ba omitted: softmax shift-invariant) ----
    for (int j = warp; j < NW12; j += 8) {
        int sseq = s0 - M_WIN + j;
        int sc = min(max(sseq, 0), SEQ - 1);
        const float* xr = bbase + (size_t)sc * H;
        float d = 0.f;
#pragma unroll
        for (int k = 0; k < 12; k++) {
            int h2 = 2 * lane + 64 * k;
            float2 v = *(const float2*)&xr[h2];
            float2 w2 = *(const float2*)&wa[h2];
            d += v.x * w2.x + v.y * w2.y;
        }
#pragma unroll
        for (int o = 16; o > 0; o >>= 1) d += __shfl_down_sync(0xffffffffu, d, o);
        if (lane == 0) scbuf[j] = d;
    }

    // ---- phase 1b: base logits for own 2 tokens per warp ----
#pragma unroll
    for (int tt = 0; tt < 2; tt++) {
        const int t = warp * 2 + tt;
        const float* xr = bbase + (size_t)(s0 + t) * H;
        float acc[L];
#pragma unroll
        for (int l = 0; l < L; l++) acc[l] = 0.f;
#pragma unroll
        for (int k = 0; k < 12; k++) {
            int h2 = 2 * lane + 64 * k;
            float2 v = *(const float2*)&xr[h2];
            const float* w0 = &Wc[(size_t)h2 * L];
#pragma unroll
            for (int l = 0; l < L; l++) acc[l] += v.x * w0[l] + v.y * w0[l + L];
        }
#pragma unroll
        for (int l = 0; l < L; l++) {
#pragma unroll
            for (int o = 16; o > 0; o >>= 1)
                acc[l] += __shfl_down_sync(0xffffffffu, acc[l], o);
        }
        if (lane == 0) {
#pragma unroll
            for (int l = 0; l < L; l++)
                g_base[(row0 + t) * L + l] = acc[l] + bc[l];
        }
    }
    __syncthreads();

    // ---- phase 2: per-token softmax (one lane per token) ----
    if (tid < TOK12) {
        const int i = tid;
        const int sseq = s0 + i;
        float e[W_WIN];
        float m = -INFINITY;
#pragma unroll
        for (int w = 0; w < W_WIN; w++) {
            int idx = sseq - M_WIN + w;
            bool v = (idx >= 0) && (idx < SEQ);
            float scv = v ? scbuf[i + w] : -INFINITY;
            e[w] = scv;
            m = fmaxf(m, scv);
        }
        float sum = 0.f;
#pragma unroll
        for (int w = 0; w < W_WIN; w++) {
            int idx = sseq - M_WIN + w;
            bool v = (idx >= 0) && (idx < SEQ);
            float ev = v ? expf(e[w] - m) : 0.f;
            e[w] = ev;
            sum += ev;
        }
        float inv = 1.f / sum;
#pragma unroll
        for (int w = 0; w < W_WIN; w++) attn[i][w] = e[w] * inv;
    }
    __syncthreads();

    // ---- phase 3: weighted context + emit [x|ctx] fp16 ----
#pragma unroll
    for (int tt = 0; tt < 2; tt++) {
        const int t = warp * 2 + tt;
        const int sseq = s0 + t;
        const float* rp[W_WIN];
        float aw[W_WIN];
#pragma unroll
        for (int w = 0; w < W_WIN; w++) {
            int idx = min(max(sseq - M_WIN + w, 0), SEQ - 1);
            rp[w] = bbase + (size_t)idx * H;
            aw[w] = attn[t][w];
        }
        __half* arow = g_A + (size_t)(row0 + t) * K2H;
#pragma unroll
        for (int k = 0; k < 12; k++) {
            int h2 = 2 * lane + 64 * k;
            float2 xc = *(const float2*)&rp[M_WIN][h2];
            float ax = 0.f, ay = 0.f;
#pragma unroll
            for (int w = 0; w < W_WIN; w++) {
                float2 v = *(const float2*)&rp[w][h2];
                ax += aw[w] * v.x;
                ay += aw[w] * v.y;
            }
            *(__half2*)&arow[h2] = __floats2half2_rn(xc.x, xc.y);
            *(__half2*)&arow[H + h2] = __floats2half2_rn(ax, ay);
        }
    }
}

// ============================================================
// K3: single-pass fp16 HMMA GEMM: g_h = [x|ctx] @ W1 + b1
// BM=128 BN=128 BK=64(halfs = 128B rows), 3-stage cp.async
// single-sync pipeline, 256 thr (8 warps: 4M x 2N, tile 32x64),
// 2 CTAs/SM (97 KB smem each)
// ============================================================
#define BM3 128
#define BN3 128
#define BK3 64
#define NIT (K2H / BK3)            // 24
#define NSTG 3
#define SA 0
#define SB (16 * 1024)
#define STAGE_BYTES (32 * 1024)
#define SMEM_TOTAL3 (1024 + NSTG * STAGE_BYTES)

__global__ __launch_bounds__(256, 2) void k3_mma(const float* __restrict__ b1)
{
    extern __shared__ char smem_raw[];
    uint32_t sraw = smem_u32(smem_raw);
    const uint32_t sbase = (sraw + 1023u) & ~1023u;

    const int tid = threadIdx.x;
    const int lane = tid & 31, wid = tid >> 5;
    const int warpM = wid & 3;        // 4 M warps
    const int warpN = wid >> 2;       // 2 N warps
    const int m0 = blockIdx.y * BM3;
    const int n0 = blockIdx.x * BN3;

    // ---- gmem load roles: thread t -> row t>>1, chunks (t&1)*4 .. +3 ----
    const int ldRow = tid >> 1;
    const int ldC0 = (tid & 1) * 4;
    const __half* gA = g_A + (size_t)(m0 + ldRow) * K2H + ldC0 * 8;
    const __half* gB = g_B + (size_t)(n0 + ldRow) * K2H + ldC0 * 8;
    uint32_t dOff[4];
#pragma unroll
    for (int i = 0; i < 4; i++) {
        int c = ldC0 + i;
        dOff[i] = ldRow * 128 + ((c ^ (ldRow & 7)) << 4);
    }

    // ---- ldmatrix address prep ----
    int aRow[2], aX[2];
    aRow[0] = warpM * 32 + (lane & 15);
    aRow[1] = aRow[0] + 16;
    aX[0] = aRow[0] & 7;
    aX[1] = aRow[1] & 7;
    const int aCB = lane >> 4;
    int bRow[4], bX[4];
#pragma unroll
    for (int p = 0; p < 4; p++) {
        bRow[p] = warpN * 64 + p * 16 + (lane & 7) + ((lane >> 4) << 3);
        bX[p] = bRow[p] & 7;
    }
    const int bCB = (lane >> 3) & 1;

    float c[2][8][4];
#pragma unroll
    for (int f = 0; f < 2; f++)
#pragma unroll
        for (int j = 0; j < 8; j++)
#pragma unroll
            for (int q = 0; q < 4; q++) c[f][j][q] = 0.f;

    // ---- prologue: stages 0..NSTG-2 ----
#pragma unroll
    for (int st = 0; st < NSTG - 1; st++) {
        uint32_t sd = sbase + st * STAGE_BYTES;
        const int kb = st * BK3;
#pragma unroll
        for (int i = 0; i < 4; i++) {
            cp16(sd + SA + dOff[i], gA + kb + i * 8);
            cp16(sd + SB + dOff[i], gB + kb + i * 8);
        }
        cp_commit();
    }

    for (int it = 0; it < NIT; ++it) {
        cp_wait<NSTG - 2>();      // stage `it` resident
        __syncthreads();          // all warps done reading stage it-1

        const int pf = it + NSTG - 1;
        if (pf < NIT) {
            const uint32_t sn = sbase + (pf % NSTG) * STAGE_BYTES;
            const int kb = pf * BK3;
#pragma unroll
            for (int i = 0; i < 4; i++) {
                cp16(sn + SA + dOff[i], gA + kb + i * 8);
                cp16(sn + SB + dOff[i], gB + kb + i * 8);
            }
        }
        cp_commit();

        const uint32_t sd = sbase + (it % NSTG) * STAGE_BYTES;
#pragma unroll
        for (int s = 0; s < 4; s++) {          // 4 k16-steps per BK=64
            uint32_t af[2][4], bf[4][4];
#pragma unroll
            for (int f = 0; f < 2; f++) {
                uint32_t off = aRow[f] * 128 + (((2 * s + aCB) ^ aX[f]) << 4);
                ldsm_x4(af[f], sd + SA + off);
            }
#pragma unroll
            for (int p = 0; p < 4; p++) {
                uint32_t off = bRow[p] * 128 + (((2 * s + bCB) ^ bX[p]) << 4);
                ldsm_x4(bf[p], sd + SB + off);
            }
#pragma unroll
            for (int p = 0; p < 4; p++)
#pragma unroll
                for (int f = 0; f < 2; f++) {
                    mma_f16(c[f][2 * p],     af[f], bf[p]);
                    mma_f16(c[f][2 * p + 1], af[f], bf[p] + 2);
                }
        }
    }

    // ---- epilogue: +b1 -> g_h ----
    const int mBase = m0 + warpM * 32 + (lane >> 2);
    const int nBase = n0 + warpN * 64 + (lane & 3) * 2;
#pragma unroll
    for (int f = 0; f < 2; f++) {
#pragma unroll
        for (int j = 0; j < 8; j++) {
            int n = nBase + j * 8;
            float b0 = b1[n], b1v = b1[n + 1];
            int m = mBase + f * 16;
            float2 o0 = make_float2(c[f][j][0] + b0, c[f][j][1] + b1v);
            float2 o1 = make_float2(c[f][j][2] + b0, c[f][j][3] + b1v);
            *(float2*)&g_h[(size_t)m * H + n] = o0;
            *(float2*)&g_h[(size_t)(m + 8) * H + n] = o1;
        }
    }
}

// ============================================================
// K4: layernorm + exact gelu + W2 + combine
// warp-per-row TWO-PASS (stats pass, then L1-hot gelu pass),
// no block barriers in main loop, low register pressure.
// 256 thr = 8 warps; each warp does 2 rows; 16 rows/block
// ============================================================
#define K4_ROWS 16
__global__ __launch_bounds__(256) void k4_ln_gelu_out(
    const float* __restrict__ gamma, const float* __restrict__ beta,
    const float* __restrict__ W2, const float* __restrict__ b2,
    float* __restrict__ out)
{
    const int tid = threadIdx.x;
    const int lane = tid & 31, wid = tid >> 5;

    __shared__ float w2s[H * L];      // 27 KB
    __shared__ float gb[2 * H];       // 6 KB
    for (int i = tid; i < H * L; i += 256) w2s[i] = W2[i];
    for (int i = tid; i < H; i += 256) { gb[i] = gamma[i]; gb[H + i] = beta[i]; }
    __syncthreads();

#pragma unroll 1
    for (int r = 0; r < 2; r++) {
        const int row = blockIdx.x * K4_ROWS + wid * 2 + r;
        const float4* hp = (const float4*)(g_h + (size_t)row * H);

        // ---- pass A: statistics only (values not held) ----
        float s1 = 0.f, s2 = 0.f;
#pragma unroll
        for (int k = 0; k < 6; k++) {
            float4 v = hp[lane + 32 * k];
            s1 += v.x + v.y + v.z + v.w;
            s2 += v.x * v.x + v.y * v.y + v.z * v.z + v.w * v.w;
        }
#pragma unroll
        for (int o = 16; o > 0; o >>= 1) {
            s1 += __shfl_xor_sync(0xffffffffu, s1, o);
            s2 += __shfl_xor_sync(0xffffffffu, s2, o);
        }
        const float mu = s1 * (1.0f / H);
        const float rstd = rsqrtf(s2 * (1.0f / H) - mu * mu + 1e-5f);

        // ---- pass B: re-read row (L1-hot), gelu + W2 ----
        float bl[L];
#pragma unroll
        for (int l = 0; l < L; l++) bl[l] = 0.f;
#pragma unroll 1
        for (int k = 0; k < 6; k++) {
            const int j = lane + 32 * k;
            float4 v = hp[j];
            float he[4] = {v.x, v.y, v.z, v.w};
#pragma unroll
            for (int e = 0; e < 4; e++) {
                int idx = 4 * j + e;
                float xv = (he[e] - mu) * rstd * gb[idx] + gb[H + idx];
                float g = xv * normcdff(xv);
                const float* w2r = &w2s[idx * L];
#pragma unroll
                for (int l = 0; l < L; l++) bl[l] += g * w2r[l];
            }
        }
#pragma unroll
        for (int l = 0; l < L; l++) {
#pragma unroll
            for (int o = 16; o > 0; o >>= 1)
                bl[l] += __shfl_down_sync(0xffffffffu, bl[l], o);
        }
        if (lane == 0) {
#pragma unroll
            for (int l = 0; l < L; l++)
                out[row * L + l] = 0.5f * g_base[row * L + l] + 0.5f * (bl[l] + b2[l]);
        }
    }
}

// ============================================================
extern "C" void kernel_launch(void* const* d_in, const int* in_sizes, int n_in,
                              void* d_out, int out_size)
{
    const float* x     = (const float*)d_in[0];
    const float* Wc    = (const float*)d_in[1];
    const float* bc    = (const float*)d_in[2];
    const float* wa    = (const float*)d_in[3];
    const float* W1    = (const float*)d_in[5];
    const float* b1    = (const float*)d_in[6];
    const float* gamma = (const float*)d_in[7];
    const float* beta  = (const float*)d_in[8];
    const float* W2    = (const float*)d_in[9];
    const float* b2    = (const float*)d_in[10];
    float* out = (float*)d_out;

    cudaFuncSetAttribute(k3_mma, cudaFuncAttributeMaxDynamicSharedMemorySize, SMEM_TOTAL3);

    kprep_w<<<dim3(H / 32, K2H / 32), dim3(32, 8)>>>(W1);
    k12_fused<<<NTOK / TOK12, 256>>>(x, wa, Wc, bc);
    k3_mma<<<dim3(H / BN3, NTOK / BM3), 256, SMEM_TOTAL3>>>(b1);
    k4_ln_gelu_out<<<NTOK / K4_ROWS, 256>>>(gamma, beta, W2, b2, out);
}